// round 2
// baseline (speedup 1.0000x reference)
#include <cuda_runtime.h>

#define DIM 128
#define DIM4 (DIM / 4)
#define MAX_NODES 50000

// Scratch for HW = H @ W (allocation-free rule: __device__ global)
__device__ float g_HW[(size_t)MAX_NODES * DIM];

// ---------------------------------------------------------------------------
// GEMM: g_HW[n, 128] = H[n, 128] @ W[128, 128]
// Block: 256 threads, 64 rows per block. Dynamic smem: W (64KB) + H tile (32KB).
// Thread (tr, tc): tr = tid/32 -> 8 rows (tr*8..+7), tc = tid%32 -> 4 cols (tc*4..+3)
// ---------------------------------------------------------------------------
__global__ void __launch_bounds__(256) gemm_kernel(const float* __restrict__ H,
                                                   const float* __restrict__ W,
                                                   int n_nodes) {
    extern __shared__ float smem[];
    float* sW = smem;               // 128*128 floats
    float* sH = smem + DIM * DIM;   // 64*128 floats

    const int tid  = threadIdx.x;
    const int row0 = blockIdx.x * 64;

    // Cooperative load of full W (16384 floats, float4)
    for (int i = tid; i < DIM * DIM4; i += 256) {
        ((float4*)sW)[i] = ((const float4*)W)[i];
    }
    // Cooperative load of 64-row H tile (8192 floats, float4), zero-pad tail
    for (int i = tid; i < 64 * DIM4; i += 256) {
        int r  = i / DIM4;
        int rr = row0 + r;
        float4 v = make_float4(0.f, 0.f, 0.f, 0.f);
        if (rr < n_nodes) v = ((const float4*)H)[(size_t)rr * DIM4 + (i % DIM4)];
        ((float4*)sH)[i] = v;
    }
    __syncthreads();

    const int tr = tid >> 5;   // 0..7
    const int tc = tid & 31;   // 0..31

    float acc[8][4];
#pragma unroll
    for (int i = 0; i < 8; i++)
#pragma unroll
        for (int j = 0; j < 4; j++) acc[i][j] = 0.f;

#pragma unroll 4
    for (int k = 0; k < DIM; k++) {
        float4 w = ((const float4*)sW)[k * DIM4 + tc];
#pragma unroll
        for (int i = 0; i < 8; i++) {
            float h = sH[(tr * 8 + i) * DIM + k];   // broadcast within warp
            acc[i][0] += h * w.x;
            acc[i][1] += h * w.y;
            acc[i][2] += h * w.z;
            acc[i][3] += h * w.w;
        }
    }

#pragma unroll
    for (int i = 0; i < 8; i++) {
        int rr = row0 + tr * 8 + i;
        if (rr < n_nodes) {
            float4 o = make_float4(acc[i][0], acc[i][1], acc[i][2], acc[i][3]);
            ((float4*)g_HW)[(size_t)rr * DIM4 + tc] = o;
        }
    }
}

// ---------------------------------------------------------------------------
// Init: out[r, :] = bias  (output is poisoned by harness; we own initialization)
// ---------------------------------------------------------------------------
__global__ void init_kernel(float* __restrict__ out, const float* __restrict__ bias,
                            int n_nodes) {
    int i = blockIdx.x * blockDim.x + threadIdx.x;
    int total = n_nodes * DIM4;
    if (i < total) {
        float4 b = ((const float4*)bias)[i & (DIM4 - 1)];
        ((float4*)out)[i] = b;
    }
}

// ---------------------------------------------------------------------------
// Scatter: for each edge e: out[rows[e], :] += vals[e] * g_HW[cols[e], :]
// One warp per edge: lane L owns float4 at column 4L. red.global.add.v4.f32
// (no-return reduction, 16B granule) into L2.
// ---------------------------------------------------------------------------
__global__ void __launch_bounds__(256) scatter_kernel(const int* __restrict__ rows,
                                                      const int* __restrict__ cols,
                                                      const float* __restrict__ vals,
                                                      float* __restrict__ out,
                                                      int n_edges) {
    int gt   = blockIdx.x * blockDim.x + threadIdx.x;
    int e    = gt >> 5;
    int lane = gt & 31;
    if (e >= n_edges) return;

    int   r = __ldg(&rows[e]);
    int   c = __ldg(&cols[e]);
    float v = __ldg(&vals[e]);

    float4 hw = ((const float4*)g_HW)[(size_t)c * DIM4 + lane];
    float4 m  = make_float4(v * hw.x, v * hw.y, v * hw.z, v * hw.w);

    float* p = out + (size_t)r * DIM + lane * 4;
    asm volatile("red.global.add.v4.f32 [%0], {%1, %2, %3, %4};"
                 :: "l"(p), "f"(m.x), "f"(m.y), "f"(m.z), "f"(m.w)
                 : "memory");
}

// ---------------------------------------------------------------------------
// Launch. Inputs (metadata order): edge_rows, edge_cols, edge_vals, H, W, bias
// Output: float32 [n_nodes, 128]
// ---------------------------------------------------------------------------
extern "C" void kernel_launch(void* const* d_in, const int* in_sizes, int n_in,
                              void* d_out, int out_size) {
    const int*   edge_rows = (const int*)d_in[0];
    const int*   edge_cols = (const int*)d_in[1];
    const float* edge_vals = (const float*)d_in[2];
    const float* H         = (const float*)d_in[3];
    const float* W         = (const float*)d_in[4];
    const float* bias      = (const float*)d_in[5];
    float*       out       = (float*)d_out;

    const int n_edges = in_sizes[0];
    const int n_nodes = in_sizes[3] / DIM;

    const int smem_bytes = (DIM * DIM + 64 * DIM) * (int)sizeof(float);  // 96 KB
    cudaFuncSetAttribute(gemm_kernel, cudaFuncAttributeMaxDynamicSharedMemorySize,
                         smem_bytes);

    // 1) out = bias (broadcast)
    {
        int total  = n_nodes * DIM4;
        int blocks = (total + 255) / 256;
        init_kernel<<<blocks, 256>>>(out, bias, n_nodes);
    }

    // 2) g_HW = H @ W
    {
        int blocks = (n_nodes + 63) / 64;
        gemm_kernel<<<blocks, 256, smem_bytes>>>(H, W, n_nodes);
    }

    // 3) out[r] += v * g_HW[c]  (warp per edge)
    {
        long long threads = (long long)n_edges * 32;
        int blocks = (int)((threads + 255) / 256);
        scatter_kernel<<<blocks, 256>>>(edge_rows, edge_cols, edge_vals, out, n_edges);
    }
}

// round 3
// speedup vs baseline: 1.3137x; 1.3137x over previous
#include <cuda_runtime.h>

#define DIM 128
#define DIM4 32
#define MAX_NODES 50000
#define MAX_EDGES 800000
#define CAP 96

// ---- device scratch (allocation-free rule: __device__ globals) -------------
__device__ float              g_HW[(size_t)MAX_NODES * DIM];      // 25.6 MB
__device__ unsigned long long g_bin[(size_t)MAX_NODES * CAP];     // 38.4 MB
__device__ int                g_cnt[MAX_NODES];
__device__ int                g_ovf_cnt;
__device__ int                g_ovf_r[MAX_EDGES];                 // full-capacity overflow
__device__ unsigned long long g_ovf_e[MAX_EDGES];

// ---------------------------------------------------------------------------
// Zero per-row counters + overflow counter
// ---------------------------------------------------------------------------
__global__ void zero_kernel(int n_nodes) {
    int i = blockIdx.x * blockDim.x + threadIdx.x;
    if (i < n_nodes) g_cnt[i] = 0;
    if (i == 0) g_ovf_cnt = 0;
}

// ---------------------------------------------------------------------------
// Bin edges by destination row. Packed slot = (val_bits << 32) | col.
// ---------------------------------------------------------------------------
__global__ void __launch_bounds__(256) bin_kernel(const int* __restrict__ rows,
                                                  const int* __restrict__ cols,
                                                  const float* __restrict__ vals,
                                                  int n_edges) {
    int e = blockIdx.x * blockDim.x + threadIdx.x;
    if (e >= n_edges) return;
    int r = rows[e];
    unsigned long long pk = (unsigned long long)(unsigned)cols[e]
                          | ((unsigned long long)__float_as_uint(vals[e]) << 32);
    int p = atomicAdd(&g_cnt[r], 1);
    if (p < CAP) {
        g_bin[(size_t)r * CAP + p] = pk;
    } else {
        int q = atomicAdd(&g_ovf_cnt, 1);
        g_ovf_r[q] = r;
        g_ovf_e[q] = pk;
    }
}

// ---------------------------------------------------------------------------
// GEMM: g_HW = H @ W using packed fma.rn.f32x2 (FFMA2).
// 256 threads, 64 rows/block. smem: W (64KB) + transposed H tile (32KB).
// Thread (tr, tc): tr -> 8 rows as 4 (i, i+1) pairs, tc -> 4 cols.
// ---------------------------------------------------------------------------
__global__ void __launch_bounds__(256) gemm_kernel(const float* __restrict__ H,
                                                   const float* __restrict__ W,
                                                   int n_nodes) {
    extern __shared__ float smem[];
    float* sW  = smem;              // [128][128]
    float* sHT = smem + DIM * DIM;  // [128 k][64 rows] (transposed)

    const int tid  = threadIdx.x;
    const int row0 = blockIdx.x * 64;

    for (int i = tid; i < DIM * DIM4; i += 256)
        ((float4*)sW)[i] = ((const float4*)W)[i];

    for (int i = tid; i < 64 * DIM4; i += 256) {
        int r  = i / DIM4;
        int k4 = (i % DIM4) * 4;
        int rr = row0 + r;
        float4 v = make_float4(0.f, 0.f, 0.f, 0.f);
        if (rr < n_nodes) v = ((const float4*)H)[(size_t)rr * DIM4 + (i % DIM4)];
        sHT[(k4 + 0) * 64 + r] = v.x;
        sHT[(k4 + 1) * 64 + r] = v.y;
        sHT[(k4 + 2) * 64 + r] = v.z;
        sHT[(k4 + 3) * 64 + r] = v.w;
    }
    __syncthreads();

    const int tr = tid >> 5;   // 0..7 -> rows tr*8 .. tr*8+7
    const int tc = tid & 31;   // 0..31 -> cols tc*4 .. tc*4+3

    unsigned long long acc[4][4];  // [i-pair][j] = packed (row 2p, row 2p+1)
#pragma unroll
    for (int p = 0; p < 4; p++)
#pragma unroll
        for (int j = 0; j < 4; j++) acc[p][j] = 0ull;

#pragma unroll 4
    for (int k = 0; k < DIM; k++) {
        float4 w = ((const float4*)sW)[k * DIM4 + tc];
        unsigned long long ws[4];
        asm("mov.b64 %0, {%1, %2};" : "=l"(ws[0]) : "f"(w.x), "f"(w.x));
        asm("mov.b64 %0, {%1, %2};" : "=l"(ws[1]) : "f"(w.y), "f"(w.y));
        asm("mov.b64 %0, {%1, %2};" : "=l"(ws[2]) : "f"(w.z), "f"(w.z));
        asm("mov.b64 %0, {%1, %2};" : "=l"(ws[3]) : "f"(w.w), "f"(w.w));
        const int base = k * 64 + tr * 8;
#pragma unroll
        for (int p = 0; p < 4; p++) {
            unsigned long long hp =
                *(const unsigned long long*)&sHT[base + 2 * p];  // (h_i, h_i+1) broadcast
            asm("fma.rn.f32x2 %0, %1, %2, %0;" : "+l"(acc[p][0]) : "l"(hp), "l"(ws[0]));
            asm("fma.rn.f32x2 %0, %1, %2, %0;" : "+l"(acc[p][1]) : "l"(hp), "l"(ws[1]));
            asm("fma.rn.f32x2 %0, %1, %2, %0;" : "+l"(acc[p][2]) : "l"(hp), "l"(ws[2]));
            asm("fma.rn.f32x2 %0, %1, %2, %0;" : "+l"(acc[p][3]) : "l"(hp), "l"(ws[3]));
        }
    }

#pragma unroll
    for (int p = 0; p < 4; p++) {
        float2 a0 = *reinterpret_cast<float2*>(&acc[p][0]);
        float2 a1 = *reinterpret_cast<float2*>(&acc[p][1]);
        float2 a2 = *reinterpret_cast<float2*>(&acc[p][2]);
        float2 a3 = *reinterpret_cast<float2*>(&acc[p][3]);
        int rr0 = row0 + tr * 8 + 2 * p;
        int rr1 = rr0 + 1;
        if (rr0 < n_nodes)
            ((float4*)g_HW)[(size_t)rr0 * DIM4 + tc] = make_float4(a0.x, a1.x, a2.x, a3.x);
        if (rr1 < n_nodes)
            ((float4*)g_HW)[(size_t)rr1 * DIM4 + tc] = make_float4(a0.y, a1.y, a2.y, a3.y);
    }
}

// ---------------------------------------------------------------------------
// SpMM: one warp per output row. out[r] = bias + sum_j val_j * g_HW[col_j].
// Register accumulation, one STG.128 per lane, no atomics.
// ---------------------------------------------------------------------------
__global__ void __launch_bounds__(256) spmm_kernel(const float* __restrict__ bias,
                                                   float* __restrict__ out,
                                                   int n_nodes) {
    int gt   = blockIdx.x * blockDim.x + threadIdx.x;
    int r    = gt >> 5;
    int lane = gt & 31;
    if (r >= n_nodes) return;

    int cnt = g_cnt[r];
    if (cnt > CAP) cnt = CAP;
    const unsigned long long* bp = &g_bin[(size_t)r * CAP];

    float4 acc = ((const float4*)bias)[lane];
#pragma unroll 4
    for (int j = 0; j < cnt; j++) {
        unsigned long long e = bp[j];
        int   c = (int)(unsigned)e;
        float v = __uint_as_float((unsigned)(e >> 32));
        float4 hw = ((const float4*)g_HW)[(size_t)c * DIM4 + lane];
        acc.x += v * hw.x;
        acc.y += v * hw.y;
        acc.z += v * hw.z;
        acc.w += v * hw.w;
    }
    ((float4*)out)[(size_t)r * DIM4 + lane] = acc;
}

// ---------------------------------------------------------------------------
// Overflow edges (none in practice for Poisson(16) degrees; correctness path).
// Runs after spmm wrote out, so RED into out is safe.
// ---------------------------------------------------------------------------
__global__ void __launch_bounds__(256) ovf_kernel(float* __restrict__ out) {
    int n = g_ovf_cnt;
    if (n <= 0) return;
    int warps = (gridDim.x * blockDim.x) >> 5;
    int w     = (blockIdx.x * blockDim.x + threadIdx.x) >> 5;
    int lane  = threadIdx.x & 31;
    for (int i = w; i < n; i += warps) {
        int r = g_ovf_r[i];
        unsigned long long e = g_ovf_e[i];
        int   c = (int)(unsigned)e;
        float v = __uint_as_float((unsigned)(e >> 32));
        float4 hw = ((const float4*)g_HW)[(size_t)c * DIM4 + lane];
        float* p = out + (size_t)r * DIM + lane * 4;
        asm volatile("red.global.add.v4.f32 [%0], {%1, %2, %3, %4};"
                     :: "l"(p), "f"(v * hw.x), "f"(v * hw.y), "f"(v * hw.z), "f"(v * hw.w)
                     : "memory");
    }
}

// ---------------------------------------------------------------------------
// Launch. Inputs: edge_rows, edge_cols, edge_vals, H, W, bias. Output f32.
// ---------------------------------------------------------------------------
extern "C" void kernel_launch(void* const* d_in, const int* in_sizes, int n_in,
                              void* d_out, int out_size) {
    const int*   edge_rows = (const int*)d_in[0];
    const int*   edge_cols = (const int*)d_in[1];
    const float* edge_vals = (const float*)d_in[2];
    const float* H         = (const float*)d_in[3];
    const float* W         = (const float*)d_in[4];
    const float* bias      = (const float*)d_in[5];
    float*       out       = (float*)d_out;

    const int n_edges = in_sizes[0];
    const int n_nodes = in_sizes[3] / DIM;

    const int gemm_smem = (DIM * DIM + 64 * DIM) * (int)sizeof(float);  // 96 KB
    cudaFuncSetAttribute(gemm_kernel, cudaFuncAttributeMaxDynamicSharedMemorySize,
                         gemm_smem);

    // 1) zero counters
    zero_kernel<<<(n_nodes + 256) / 256, 256>>>(n_nodes);

    // 2) bin edges by destination row
    bin_kernel<<<(n_edges + 255) / 256, 256>>>(edge_rows, edge_cols, edge_vals, n_edges);

    // 3) g_HW = H @ W  (FFMA2)
    gemm_kernel<<<(n_nodes + 63) / 64, 256, gemm_smem>>>(H, W, n_nodes);

    // 4) out = bias + row-gathered sum (no atomics)
    {
        long long threads = (long long)n_nodes * 32;
        spmm_kernel<<<(int)((threads + 255) / 256), 256>>>(bias, out, n_nodes);
    }

    // 5) overflow correctness path (empty in practice)
    ovf_kernel<<<32, 256>>>(out);
}